// round 2
// baseline (speedup 1.0000x reference)
#include <cuda_runtime.h>

#define FULLMASK 0xffffffffu

constexpr int Nn = 8;
constexpr int Cc = 128;
constexpr int Hh = 160;
constexpr int Ww = 160;
constexpr int HWC = Hh * Ww * Cc;        // per-image NHWC stride
constexpr int TOT = Nn * HWC;            // 26,214,400

// Ping-pong NHWC scratch (allowed: static __device__ arrays, no runtime alloc)
__device__ float g_bufA[TOT];
__device__ float g_bufB[TOT];

// One scan step: carry d0..d3 (pre-relu state, 4 consecutive channels per lane),
// conv along C via lane shuffles, zero-padded at C boundaries.
// d_new = relu(conv(d) + b) + x
__device__ __forceinline__ void scan_step(float& d0, float& d1, float& d2, float& d3,
                                          float x0, float x1, float x2, float x3,
                                          const float wk[9], float b, int lane)
{
    float v[12];
    v[4] = d0; v[5] = d1; v[6] = d2; v[7] = d3;
    v[0]  = __shfl_up_sync(FULLMASK, d0, 1);
    v[1]  = __shfl_up_sync(FULLMASK, d1, 1);
    v[2]  = __shfl_up_sync(FULLMASK, d2, 1);
    v[3]  = __shfl_up_sync(FULLMASK, d3, 1);
    v[8]  = __shfl_down_sync(FULLMASK, d0, 1);
    v[9]  = __shfl_down_sync(FULLMASK, d1, 1);
    v[10] = __shfl_down_sync(FULLMASK, d2, 1);
    v[11] = __shfl_down_sync(FULLMASK, d3, 1);
    if (lane == 0)  { v[0] = 0.f; v[1] = 0.f; v[2]  = 0.f; v[3]  = 0.f; }
    if (lane == 31) { v[8] = 0.f; v[9] = 0.f; v[10] = 0.f; v[11] = 0.f; }
    float a0 = b, a1 = b, a2 = b, a3 = b;
#pragma unroll
    for (int k = 0; k < 9; k++) {
        a0 = fmaf(wk[k], v[k + 0], a0);
        a1 = fmaf(wk[k], v[k + 1], a1);
        a2 = fmaf(wk[k], v[k + 2], a2);
        a3 = fmaf(wk[k], v[k + 3], a3);
    }
    d0 = fmaxf(a0, 0.f) + x0;
    d1 = fmaxf(a1, 0.f) + x1;
    d2 = fmaxf(a2, 0.f) + x2;
    d3 = fmaxf(a3, 0.f) + x3;
}

// Generic NHWC->NHWC scan over one column. inp/outp point at the FIRST scan
// element (+c0). stride is signed (floats) to cover ascending/descending.
__device__ __forceinline__ void scan_col(const float* __restrict__ inp,
                                         float* __restrict__ outp,
                                         int stride, const float wk[9], float b, int lane)
{
    float4 v0 = *(const float4*)inp;
    float d0 = v0.x, d1 = v0.y, d2 = v0.z, d3 = v0.w;
    *(float4*)outp = make_float4(fmaxf(d0, 0.f), fmaxf(d1, 0.f), fmaxf(d2, 0.f), fmaxf(d3, 0.f));
    float4 nx = *(const float4*)(inp + stride);
#pragma unroll 4
    for (int t = 1; t < 160; t++) {
        float4 cx = nx;
        if (t < 159) nx = *(const float4*)(inp + (t + 1) * stride);
        scan_step(d0, d1, d2, d3, cx.x, cx.y, cx.z, cx.w, wk, b, lane);
        *(float4*)(outp + t * stride) =
            make_float4(fmaxf(d0, 0.f), fmaxf(d1, 0.f), fmaxf(d2, 0.f), fmaxf(d3, 0.f));
    }
}

// Pass 1 (down, scan over H ascending): reads x in NCHW, writes NHWC g_bufA.
__global__ void __launch_bounds__(128) k_pass1(const float* __restrict__ x,
                                               const float* __restrict__ wgt,
                                               const float* __restrict__ bia)
{
    const int lane = threadIdx.x & 31, warp = threadIdx.x >> 5;
    const int col = blockIdx.x * 4 + warp;   // n*W + w
    const int n = col / Ww, w = col % Ww;
    float wk[9];
#pragma unroll
    for (int k = 0; k < 9; k++) wk[k] = wgt[k];
    const float b = bia[0];
    const int c0 = lane * 4;

    // NCHW: x[((n*C + c)*H + h)*W + w]
    const float* xc = x + (size_t)n * Cc * Hh * Ww + (size_t)c0 * Hh * Ww + w;
    const int HW = Hh * Ww;
    // NHWC out: g_bufA[((n*H + h)*W + w)*C + c]
    float* ob = g_bufA + (size_t)n * HWC + (size_t)w * Cc + c0;

    // h = 0: carry = x[0]
    float d0 = xc[0 * HW];
    float d1 = xc[1 * HW];
    float d2 = xc[2 * HW];
    float d3 = xc[3 * HW];
    *(float4*)ob = make_float4(fmaxf(d0, 0.f), fmaxf(d1, 0.f), fmaxf(d2, 0.f), fmaxf(d3, 0.f));

    float n0 = xc[0 * HW + Ww], n1 = xc[1 * HW + Ww], n2 = xc[2 * HW + Ww], n3 = xc[3 * HW + Ww];
    for (int h = 1; h < Hh; h++) {
        float cx0 = n0, cx1 = n1, cx2 = n2, cx3 = n3;
        if (h < Hh - 1) {
            const int o = (h + 1) * Ww;
            n0 = xc[0 * HW + o]; n1 = xc[1 * HW + o];
            n2 = xc[2 * HW + o]; n3 = xc[3 * HW + o];
        }
        scan_step(d0, d1, d2, d3, cx0, cx1, cx2, cx3, wk, b, lane);
        *(float4*)(ob + h * (Ww * Cc)) =
            make_float4(fmaxf(d0, 0.f), fmaxf(d1, 0.f), fmaxf(d2, 0.f), fmaxf(d3, 0.f));
    }
}

// Pass 2 (up, scan over H descending): g_bufA -> g_bufB, NHWC.
__global__ void __launch_bounds__(128) k_pass2(const float* __restrict__ wgt,
                                               const float* __restrict__ bia)
{
    const int lane = threadIdx.x & 31, warp = threadIdx.x >> 5;
    const int col = blockIdx.x * 4 + warp;   // n*W + w
    const int n = col / Ww, w = col % Ww;
    float wk[9];
#pragma unroll
    for (int k = 0; k < 9; k++) wk[k] = wgt[k];
    const float b = bia[0];
    const int c0 = lane * 4;
    const int base = n * HWC + (Hh - 1) * (Ww * Cc) + w * Cc + c0;  // start at h = H-1
    scan_col(g_bufA + base, g_bufB + base, -(Ww * Cc), wk, b, lane);
}

// Pass 3 (left, scan over W ascending): g_bufB -> g_bufA, NHWC.
__global__ void __launch_bounds__(128) k_pass3(const float* __restrict__ wgt,
                                               const float* __restrict__ bia)
{
    const int lane = threadIdx.x & 31, warp = threadIdx.x >> 5;
    const int col = blockIdx.x * 4 + warp;   // n*H + h
    const int n = col / Hh, h = col % Hh;
    float wk[9];
#pragma unroll
    for (int k = 0; k < 9; k++) wk[k] = wgt[k];
    const float b = bia[0];
    const int c0 = lane * 4;
    const int base = n * HWC + h * (Ww * Cc) + c0;                   // start at w = 0
    scan_col(g_bufB + base, g_bufA + base, Cc, wk, b, lane);
}

// Pass 4 (right, scan over W descending): g_bufA (NHWC) -> d_out in NCHW with
// both spatial axes flipped (reference never un-flips). Output staged in smem
// per 16-step tile so NCHW stores are 64B-contiguous rows.
__global__ void __launch_bounds__(128) k_pass4(const float* __restrict__ wgt,
                                               const float* __restrict__ bia,
                                               float* __restrict__ out)
{
    __shared__ float stage[4][16][128];   // [warp(h)][tile-w][c] = 32 KB
    const int lane = threadIdx.x & 31, warp = threadIdx.x >> 5;
    const int col = blockIdx.x * 4 + warp;   // n*H + h
    const int n = col / Hh, h = col % Hh;
    const int col0 = blockIdx.x * 4;         // 4|160 so whole block shares n
    const int nb = col0 / Hh, hb = col0 % Hh;
    float wk[9];
#pragma unroll
    for (int k = 0; k < 9; k++) wk[k] = wgt[k];
    const float b = bia[0];
    const int c0 = lane * 4;

    const float* inp = g_bufA + n * HWC + h * (Ww * Cc) + c0;  // + w*Cc

    // w = W-1 (s = 0): carry = A3[W-1]
    float4 v0 = *(const float4*)(inp + (Ww - 1) * Cc);
    float d0 = v0.x, d1 = v0.y, d2 = v0.z, d3 = v0.w;
    *(float4*)&stage[warp][0][c0] =
        make_float4(fmaxf(d0, 0.f), fmaxf(d1, 0.f), fmaxf(d2, 0.f), fmaxf(d3, 0.f));

    float4 nx = *(const float4*)(inp + (Ww - 2) * Cc);
    for (int w = Ww - 2; w >= 0; w--) {
        const int s = (Ww - 1) - w;          // output w index, ascending
        float4 cx = nx;
        if (w > 0) nx = *(const float4*)(inp + (w - 1) * Cc);
        scan_step(d0, d1, d2, d3, cx.x, cx.y, cx.z, cx.w, wk, b, lane);
        *(float4*)&stage[warp][s & 15][c0] =
            make_float4(fmaxf(d0, 0.f), fmaxf(d1, 0.f), fmaxf(d2, 0.f), fmaxf(d3, 0.f));

        if ((s & 15) == 15) {                // flush 16-wide output tile
            __syncthreads();
            const int s0 = s - 15;
#pragma unroll
            for (int k = 0; k < 4; k++) {
                const int row = k * 128 + threadIdx.x;   // 512 rows: (h-in-block, c)
                const int j = row >> 7, c = row & 127;
                float* op = out + (((size_t)nb * Cc + c) * Hh + (Hh - 1 - (hb + j))) * Ww + s0;
#pragma unroll
                for (int t = 0; t < 4; t++) {
                    float4 val = make_float4(stage[j][4 * t + 0][c], stage[j][4 * t + 1][c],
                                             stage[j][4 * t + 2][c], stage[j][4 * t + 3][c]);
                    ((float4*)op)[t] = val;
                }
            }
            __syncthreads();
        }
    }
}

extern "C" void kernel_launch(void* const* d_in, const int* in_sizes, int n_in,
                              void* d_out, int out_size)
{
    (void)in_sizes; (void)n_in; (void)out_size;
    const float* x  = (const float*)d_in[0];
    const float* wd = (const float*)d_in[1];
    const float* bd = (const float*)d_in[2];
    const float* wu = (const float*)d_in[3];
    const float* bu = (const float*)d_in[4];
    const float* wl = (const float*)d_in[5];
    const float* bl = (const float*)d_in[6];
    const float* wr = (const float*)d_in[7];
    const float* br = (const float*)d_in[8];
    float* out = (float*)d_out;

    k_pass1<<<320, 128>>>(x, wd, bd);
    k_pass2<<<320, 128>>>(wu, bu);
    k_pass3<<<320, 128>>>(wl, bl);
    k_pass4<<<320, 128>>>(wr, br, out);
}